// round 17
// baseline (speedup 1.0000x reference)
#include <cuda_runtime.h>

// Grouped shifted conv:
//   t = roll(x, +1, axis=W); tp = zero-pad t by 1 on W
//   y[o*16+k, n, m] = sum_{i<64, j<3} tp[o*64+i, n, m+j] * W[i,k,j]
//   out[c, n, m] = y[c, (n-1)%56, m]   (roll +1 along H)
//
// Zero-staging design: x is read directly from global (L1-resident, 16-fold
// reuse across k); only W is staged to shared (one barrier, the kernel's
// only sync). No ts[] staging, no psum, no reduce. Grid (56, 2) = 112 CTAs
// (one balanced wave), 224 threads = 16 k x 14 m-quads, 4 outputs/thread,
// full 64-channel reduction per thread.
//
// Tap window for outputs m..m+3 is tp[m..m+5]:
//   interior: tp[m..m+5] = x[m-2..m+3]
//   m = 0   : tp[0]=0, tp[1]=x[55], tp[2..5]=x[0..3]
//   m = 52  : tp[52..56]=x[50..54], tp[57]=0
// Both edges unify to: L2 = float2 at (m==0 ? 54 : m-2), B4 = float4 at m,
// t0 = (m==0 ? 0 : L2.x), t1 = L2.y, t2..t4 = B4.xyz, t5 = (m==52 ? 0 : B4.w).

#define NTHREADS 224

__global__ __launch_bounds__(NTHREADS) void shiftconv_kernel(
    const float* __restrict__ x,   // (128, 56, 56)
    const float* __restrict__ W,   // (64, 16, 3)
    float* __restrict__ out)       // (32, 56, 56)
{
    __shared__ float4 Ws4[64 * 16];        // W[i][k][0..2], .w unused

    const int np  = blockIdx.x;            // input H-row n'
    const int o   = blockIdx.y;            // channel group
    const int tid = threadIdx.x;

    // ---- Stage W (1024 entries over 224 threads), the only barrier ----
    for (int e = tid; e < 1024; e += NTHREADS) {
        const float* wp = W + e * 3;       // row-major (64,16,3): (i*16+k)*3
        Ws4[e] = make_float4(wp[0], wp[1], wp[2], 0.0f);
    }
    __syncthreads();

    const int k  = tid / 14;
    const int mq = tid - k * 14;
    const int m  = mq * 4;

    const bool first = (m == 0);
    const bool last  = (m == 52);
    const int  off2  = first ? 54 : (m - 2);

    const float* xbase = x + (o * 64) * 3136 + np * 56;

    float a0 = 0.f, a1 = 0.f, a2 = 0.f, a3 = 0.f;
    #pragma unroll 8
    for (int i = 0; i < 64; i++) {
        const float* row = xbase + i * 3136;
        const float2 L2 = *reinterpret_cast<const float2*>(row + off2);
        const float4 B4 = *reinterpret_cast<const float4*>(row + m);
        const float4 w  = Ws4[i * 16 + k];

        const float t0 = first ? 0.0f : L2.x;
        const float t1 = L2.y;
        const float t5 = last ? 0.0f : B4.w;

        a0 += t0   * w.x + t1   * w.y + B4.x * w.z;
        a1 += t1   * w.x + B4.x * w.y + B4.y * w.z;
        a2 += B4.x * w.x + B4.y * w.y + B4.z * w.z;
        a3 += B4.y * w.x + B4.z * w.y + t5   * w.z;
    }

    // Output H-roll: y row n' lands at out row (n'+1)%56.
    int nout = np + 1; if (nout >= 56) nout -= 56;
    *reinterpret_cast<float4*>(
        out + (o * 16 + k) * 3136 + nout * 56 + m) =
        make_float4(a0, a1, a2, a3);
}

extern "C" void kernel_launch(void* const* d_in, const int* in_sizes, int n_in,
                              void* d_out, int out_size) {
    const float* x = (const float*)d_in[0];   // 128*56*56 = 401408
    const float* W = (const float*)d_in[1];   // 64*16*3   = 3072
    float* out     = (float*)d_out;           // 32*56*56  = 100352

    dim3 grid(56, 2);
    shiftconv_kernel<<<grid, NTHREADS>>>(x, W, out);
}